// round 5
// baseline (speedup 1.0000x reference)
#include <cuda_runtime.h>
#include <cuda_bf16.h>
#include <cstdint>
#include <math.h>

#define T_HRZ 1024
#define NB    128
#define NU    64
#define NY    64
#define NH    256
#define NPAIR 128
#define NCHUNK 64
#define LCHUNK 16

// ---------------- scratch -----------------------------------------------------
__device__ float  g_Bu[(size_t)T_HRZ * NB * NH];     // paired n' layout, 134 MB
__device__ float2 g_F[NCHUNK * NB * NPAIR];
__device__ float2 g_S[NCHUNK * NB * NPAIR];
__device__ float  g_lr[NPAIR], g_li[NPAIR], g_nf[NPAIR];
__device__ float2 g_lamL[NPAIR];
// GEMM1 B operand, PAIRED row order n'=2j(re)/2j+1(im), bf16 hi/lo, [256][64]
__device__ __align__(16) uint16_t g_Bph[NH * NU], g_Bpl[NH * NU];
// GEMM2 W operand, k' PERMUTED to paired order, bf16 hi/lo, [64][256]
__device__ __align__(16) uint16_t g_Wph[NY * NH], g_Wpl[NY * NH];

// ---------------- helpers -----------------------------------------------------
__device__ __forceinline__ uint32_t smem_u32(const void* p) {
    uint32_t a;
    asm("{ .reg .u64 t; cvta.to.shared.u64 t, %1; cvt.u32.u64 %0, t; }" : "=r"(a) : "l"(p));
    return a;
}
__device__ __forceinline__ void cvt_hilo(float f, uint16_t& h, uint16_t& l) {
    __nv_bfloat16 hb = __float2bfloat16(f);
    float fh = __bfloat162float(hb);
    __nv_bfloat16 lb = __float2bfloat16(f - fh);
    h = __bfloat16_as_ushort(hb);
    l = __bfloat16_as_ushort(lb);
}
__device__ __forceinline__ void mma16816(float* c, const uint32_t* a,
                                         uint32_t b0, uint32_t b1) {
    asm volatile(
        "mma.sync.aligned.m16n8k16.row.col.f32.bf16.bf16.f32 "
        "{%0,%1,%2,%3}, {%4,%5,%6,%7}, {%8,%9}, {%0,%1,%2,%3};"
        : "+f"(c[0]), "+f"(c[1]), "+f"(c[2]), "+f"(c[3])
        : "r"(a[0]), "r"(a[1]), "r"(a[2]), "r"(a[3]), "r"(b0), "r"(b1));
}
__device__ __forceinline__ void ldsm_x4(uint32_t* r, uint32_t addr) {
    asm volatile("ldmatrix.sync.aligned.m8n8.x4.shared.b16 {%0,%1,%2,%3}, [%4];"
                 : "=r"(r[0]), "=r"(r[1]), "=r"(r[2]), "=r"(r[3]) : "r"(addr));
}
__device__ __forceinline__ void ldsm_x2(uint32_t& r0, uint32_t& r1, uint32_t addr) {
    asm volatile("ldmatrix.sync.aligned.m8n8.x2.shared.b16 {%0,%1}, [%2];"
                 : "=r"(r0), "=r"(r1) : "r"(addr));
}

// ---------------- K0: params ---------------------------------------------------
__global__ void params_kernel(const float* __restrict__ lrc, const float* __restrict__ lic) {
    int j = threadIdx.x;
    if (j < NPAIR) {
        float a = fabsf(lrc[j]);
        float r = expf(-a);
        float th = 1.5707963267948966f * lic[j];
        float lr = r * cosf(th), li = r * sinf(th);
        g_lr[j] = lr; g_li[j] = li;
        g_nf[j] = sqrtf(1.0f - expf(-2.0f * a));
        float wr = 1.0f, wi = 0.0f;
        for (int l = 0; l < LCHUNK; ++l) {
            float nr = wr * lr - wi * li;
            wi = wr * li + wi * lr; wr = nr;
        }
        g_lamL[j] = make_float2(wr, wi);
    }
}

// ---------------- K0b: operand prep --------------------------------------------
__global__ void prep_kernel(const float* __restrict__ B, const float* __restrict__ W) {
    int i = blockIdx.x * 256 + threadIdx.x;
    if (i < NH * NU) {
        int np = i >> 6, k = i & 63;
        int j = np >> 1, p = np & 1;
        float v = B[(size_t)(j + p * NPAIR) * NU + k] * g_nf[j];
        cvt_hilo(v, g_Bph[i], g_Bpl[i]);
    }
    if (i < NY * NH) {
        int n = i >> 8, kk = i & 255;
        int j = kk >> 1, p = kk & 1;
        cvt_hilo(W[(size_t)n * NH + j + p * NPAIR], g_Wph[i], g_Wpl[i]);
    }
}

// ---------------- x0 = y0 @ Wy2x^T + b ------------------------------------------
__global__ void __launch_bounds__(128) x0_kernel(const float* __restrict__ y0,
                                                 const float* __restrict__ W,
                                                 const float* __restrict__ bias) {
    __shared__ float Ws[128 * 65];
    __shared__ float ys[64];
    int b = blockIdx.x, tid = threadIdx.x;
    if (tid < 64) ys[tid] = y0[(size_t)b * NY + tid];
    float xr = 0.0f, xi = 0.0f;
#pragma unroll
    for (int half = 0; half < 2; ++half) {
        const float4* src = (const float4*)(W + (size_t)half * 128 * NY);
        for (int i = tid; i < 2048; i += 128) {
            float4 v = src[i];
            int r = i >> 4, cc = (i & 15) * 4;
            float* d = &Ws[r * 65 + cc];
            d[0] = v.x; d[1] = v.y; d[2] = v.z; d[3] = v.w;
        }
        __syncthreads();
        float acc = bias[tid + half * 128];
        const float* w = &Ws[tid * 65];
#pragma unroll
        for (int y = 0; y < NY; ++y) acc = fmaf(ys[y], w[y], acc);
        if (half == 0) xr = acc; else xi = acc;
        __syncthreads();
    }
    g_S[b * NPAIR + tid] = make_float2(xr, xi);
}

// ---------------- carry scan (streamed, NCHUNK=64) ------------------------------
__global__ void __launch_bounds__(256) carry_kernel() {
    int gtid = blockIdx.x * 256 + threadIdx.x;   // 16384
    int j = gtid & (NPAIR - 1);
    int b = gtid >> 7;
    float2 s = g_S[b * NPAIR + j];
    float2 w = g_lamL[j];
    float xr = s.x, xi = s.y;
#pragma unroll 4
    for (int c = 1; c < NCHUNK; ++c) {
        float2 f = g_F[((c - 1) * NB + b) * NPAIR + j];
        float nr = fmaf(w.x, xr, fmaf(-w.y, xi, f.x));
        float ni = fmaf(w.y, xr, fmaf(w.x, xi, f.y));
        xr = nr; xi = ni;
        g_S[(c * NB + b) * NPAIR + j] = make_float2(xr, xi);
    }
}

// ===================== fused kernels ============================================
#define PA 136                      // G1 smem pitch (halves): 64 hi | 64 lo | 8 pad
#define PX 520                      // G2 smem pitch (halves): 256 hi | 256 lo | 8 pad
#define BS_BYTES (256 * PA * 2)     // 69632
#define UB_BYTES (2 * 16 * PA * 2)  // 8704
#define WP_BYTES (64 * PX * 2)      // 66560
#define XT_BYTES (16 * PX * 2)      // 16640

#define KA_SMEM (BS_BYTES + UB_BYTES)            // 78336
#define KB_SMEM (WP_BYTES + 2 * XT_BYTES)        // 99840

__device__ __forceinline__ void fill_Bs(uint16_t* Bs, int tid) {
#pragma unroll
    for (int it = 0; it < 8; ++it) {
        int i = it * 256 + tid;
        int n = i >> 3, k8 = (i & 7) * 8;
        *(uint4*)&Bs[n * PA + k8]      = ((const uint4*)g_Bph)[i];
        *(uint4*)&Bs[n * PA + 64 + k8] = ((const uint4*)g_Bpl)[i];
    }
}
__device__ __forceinline__ void store_U(uint16_t* Ub, int buf, int row, int k4, float4 v) {
    uint16_t h0,l0,h1,l1,h2,l2,h3,l3;
    cvt_hilo(v.x,h0,l0); cvt_hilo(v.y,h1,l1); cvt_hilo(v.z,h2,l2); cvt_hilo(v.w,h3,l3);
    uint16_t* p = Ub + buf * 16 * PA + row * PA;
    *(uint2*)&p[k4]      = make_uint2(h0 | ((uint32_t)h1 << 16), h2 | ((uint32_t)h3 << 16));
    *(uint2*)&p[64 + k4] = make_uint2(l0 | ((uint32_t)l1 << 16), l2 | ((uint32_t)l3 << 16));
}

__device__ __forceinline__ void g1_mma(float C[4][4], uint32_t sU, uint32_t sB,
                                       int buf, int lane, int n0) {
    const int r8 = lane & 7;
    const uint32_t aRow = (uint32_t)(buf * 16 * PA + (r8 + ((lane >> 3) & 1) * 8) * PA) * 2;
    const uint32_t aCol = (uint32_t)(((lane >> 4) & 1) * 8) * 2;
    const uint32_t bRowBase = (uint32_t)((n0 + r8 + ((lane >> 4) & 1) * 8) * PA) * 2;
    const uint32_t bCol = (uint32_t)(((lane >> 3) & 1) * 8) * 2;
#pragma unroll
    for (int ks = 0; ks < 4; ++ks) {
        const uint32_t kb = ks * 32;
        uint32_t ah[4], al[4];
        ldsm_x4(ah, sU + aRow + aCol + kb);
        ldsm_x4(al, sU + aRow + aCol + kb + 128);
#pragma unroll
        for (int fp = 0; fp < 2; ++fp) {
            uint32_t bh[4], bl[4];
            uint32_t ro = bRowBase + (uint32_t)(fp * 16 * PA) * 2;
            ldsm_x4(bh, sB + ro + bCol + kb);
            ldsm_x4(bl, sB + ro + bCol + kb + 128);
            mma16816(C[fp*2],   ah, bh[0], bh[1]);
            mma16816(C[fp*2],   ah, bl[0], bl[1]);
            mma16816(C[fp*2],   al, bh[0], bh[1]);
            mma16816(C[fp*2+1], ah, bh[2], bh[3]);
            mma16816(C[fp*2+1], ah, bl[2], bl[3]);
            mma16816(C[fp*2+1], al, bh[2], bh[3]);
        }
    }
}

// ---------------- K_A: fused GEMM1 + scan pass A + Bu store ---------------------
__global__ void __launch_bounds__(256, 2) fused_passA(const float* __restrict__ U) {
    extern __shared__ char smem[];
    uint16_t* Bs = (uint16_t*)smem;
    uint16_t* Ub = (uint16_t*)(smem + BS_BYTES);
    const uint32_t sB = smem_u32(Bs), sU = smem_u32(Ub);
    const int tid = threadIdx.x, wid = tid >> 5, lane = tid & 31;
    const int g = lane >> 2, q = lane & 3;
    const int c = blockIdx.x >> 3, bt = blockIdx.x & 7;
    const int b0 = bt * 16, n0 = wid * 32;

    fill_Bs(Bs, tid);

    float ar[4], ai[4], xr[4][2], xi[4][2];
#pragma unroll
    for (int f = 0; f < 4; ++f) {
        int j = (n0 + f * 8 + 2 * q) >> 1;
        ar[f] = g_lr[j]; ai[f] = g_li[j];
        xr[f][0]=xr[f][1]=0.f; xi[f][0]=xi[f][1]=0.f;
    }

    const int urow = tid >> 4, uk4 = (tid & 15) * 4;
    const float* up = U + ((size_t)(c * LCHUNK) * NB + b0 + urow) * NU + uk4;
    const size_t ustep = (size_t)NB * NU;
    store_U(Ub, 0, urow, uk4, *(const float4*)up);
    __syncthreads();

    float* buBase = g_Bu + ((size_t)(c * LCHUNK) * NB + b0 + g) * NH + n0 + 2 * q;

#pragma unroll 1
    for (int lt = 0; lt < LCHUNK; ++lt) {
        float4 un;
        if (lt + 1 < LCHUNK) un = *(const float4*)(up + (lt + 1) * ustep);
        float C[4][4];
#pragma unroll
        for (int f = 0; f < 4; ++f)
#pragma unroll
            for (int e = 0; e < 4; ++e) C[f][e] = 0.0f;

        g1_mma(C, sU, sB, lt & 1, lane, n0);

        // store Bu tile + scan update
        float* bu = buBase + (size_t)lt * NB * NH;
#pragma unroll
        for (int f = 0; f < 4; ++f)
#pragma unroll
            for (int r = 0; r < 2; ++r) {
                *(float2*)(bu + (size_t)(8 * r) * NH + f * 8) =
                    make_float2(C[f][r*2], C[f][r*2+1]);
                float nr = fmaf(ar[f], xr[f][r], fmaf(-ai[f], xi[f][r], C[f][r*2]));
                float ni = fmaf(ai[f], xr[f][r], fmaf( ar[f], xi[f][r], C[f][r*2+1]));
                xr[f][r] = nr; xi[f][r] = ni;
            }
        if (lt + 1 < LCHUNK) store_U(Ub, (lt + 1) & 1, urow, uk4, un);
        __syncthreads();
    }
#pragma unroll
    for (int f = 0; f < 4; ++f)
#pragma unroll
        for (int r = 0; r < 2; ++r) {
            int b = b0 + g + r * 8;
            int j = (n0 + f * 8 + 2 * q) >> 1;
            g_F[(c * NB + b) * NPAIR + j] = make_float2(xr[f][r], xi[f][r]);
        }
}

// ---------------- K_B: Bu-read + scan pass B + GEMM2 ----------------------------
__global__ void __launch_bounds__(256, 2) fused_passB(const float* __restrict__ bias,
                                                      float* __restrict__ Y) {
    extern __shared__ char smem[];
    uint16_t* Wp = (uint16_t*)smem;
    uint16_t* Xt = (uint16_t*)(smem + WP_BYTES);
    const uint32_t sW = smem_u32(Wp), sX = smem_u32(Xt);
    const int tid = threadIdx.x, wid = tid >> 5, lane = tid & 31;
    const int g = lane >> 2, q = lane & 3;
    const int c = blockIdx.x >> 3, bt = blockIdx.x & 7;
    const int b0 = bt * 16, n0 = wid * 32, n0y = wid * 8;

#pragma unroll
    for (int it = 0; it < 8; ++it) {
        int i = it * 256 + tid;
        int n = i >> 5, k8 = (i & 31) * 8;
        *(uint4*)&Wp[n * PX + k8]       = ((const uint4*)g_Wph)[i];
        *(uint4*)&Wp[n * PX + 256 + k8] = ((const uint4*)g_Wpl)[i];
    }

    float ar[4], ai[4], xr[4][2], xi[4][2];
#pragma unroll
    for (int f = 0; f < 4; ++f) {
        int j = (n0 + f * 8 + 2 * q) >> 1;
        ar[f] = g_lr[j]; ai[f] = g_li[j];
#pragma unroll
        for (int r = 0; r < 2; ++r) {
            int b = b0 + g + r * 8;
            float2 s = g_S[(c * NB + b) * NPAIR + j];
            xr[f][r] = s.x; xi[f][r] = s.y;
        }
    }
    const float by0 = bias[n0y + 2 * q], by1 = bias[n0y + 2 * q + 1];

    const float* buBase = g_Bu + ((size_t)(c * LCHUNK) * NB + b0 + g) * NH + n0 + 2 * q;
    float2 buc[4][2], bun[4][2];
#pragma unroll
    for (int f = 0; f < 4; ++f)
#pragma unroll
        for (int r = 0; r < 2; ++r)
            buc[f][r] = *(const float2*)(buBase + (size_t)(8 * r) * NH + f * 8);

    const int r8 = lane & 7;
    const uint32_t xRowL = (uint32_t)((r8 + ((lane >> 3) & 1) * 8) * PX) * 2;
    const uint32_t xCol = (uint32_t)(((lane >> 4) & 1) * 8) * 2;
    const uint32_t wRow = (uint32_t)((n0y + r8) * PX) * 2;
    const uint32_t wCol = (uint32_t)(((lane >> 3) & 1) * 8) * 2;

    __syncthreads();

#pragma unroll 1
    for (int lt = 0; lt < LCHUNK; ++lt) {
        // prefetch next Bu tile
        if (lt + 1 < LCHUNK) {
            const float* bu = buBase + (size_t)(lt + 1) * NB * NH;
#pragma unroll
            for (int f = 0; f < 4; ++f)
#pragma unroll
                for (int r = 0; r < 2; ++r)
                    bun[f][r] = *(const float2*)(bu + (size_t)(8 * r) * NH + f * 8);
        }
        // scan update + write X tile (buffer lt&1)
        const int buf = lt & 1;
        uint16_t* Xb = Xt + buf * (16 * PX);
#pragma unroll
        for (int f = 0; f < 4; ++f)
#pragma unroll
            for (int r = 0; r < 2; ++r) {
                float nr = fmaf(ar[f], xr[f][r], fmaf(-ai[f], xi[f][r], buc[f][r].x));
                float ni = fmaf(ai[f], xr[f][r], fmaf( ar[f], xi[f][r], buc[f][r].y));
                xr[f][r] = nr; xi[f][r] = ni;
                uint16_t hr, lr_, hi_, li_;
                cvt_hilo(nr, hr, lr_); cvt_hilo(ni, hi_, li_);
                int row = g + r * 8;
                int col = n0 + f * 8 + 2 * q;
                *(uint32_t*)&Xb[row * PX + col]       = hr  | ((uint32_t)hi_ << 16);
                *(uint32_t*)&Xb[row * PX + 256 + col] = lr_ | ((uint32_t)li_ << 16);
            }
        __syncthreads();

        // GEMM2: Y tile
        float C2[4] = {0.f, 0.f, 0.f, 0.f};
        const uint32_t xBuf = (uint32_t)(buf * 16 * PX) * 2;
#pragma unroll
        for (int ks = 0; ks < 16; ++ks) {
            const uint32_t kb = ks * 32;
            uint32_t ah[4], al[4];
            ldsm_x4(ah, sX + xBuf + xRowL + xCol + kb);
            ldsm_x4(al, sX + xBuf + xRowL + xCol + kb + 512);
            uint32_t bh0, bh1, bl0, bl1;
            ldsm_x2(bh0, bh1, sW + wRow + wCol + kb);
            ldsm_x2(bl0, bl1, sW + wRow + wCol + kb + 512);
            mma16816(C2, ah, bh0, bh1);
            mma16816(C2, ah, bl0, bl1);
            mma16816(C2, al, bh0, bh1);
        }
        const int gt = c * LCHUNK + lt;
        float* y0p = Y + ((size_t)gt * NB + b0 + g) * NY + n0y + 2 * q;
        *(float2*)y0p = make_float2(C2[0] + by0, C2[1] + by1);
        *(float2*)(y0p + 8 * NY) = make_float2(C2[2] + by0, C2[3] + by1);

#pragma unroll
        for (int f = 0; f < 4; ++f)
#pragma unroll
            for (int r = 0; r < 2; ++r) buc[f][r] = bun[f][r];
    }
}

// ---------------- launch --------------------------------------------------------
extern "C" void kernel_launch(void* const* d_in, const int* in_sizes, int n_in,
                              void* d_out, int out_size) {
    const float* y0   = (const float*)d_in[0];
    const float* U    = (const float*)d_in[1];
    const float* lrc  = (const float*)d_in[2];
    const float* lic  = (const float*)d_in[3];
    const float* B    = (const float*)d_in[4];
    const float* Wy2x = (const float*)d_in[5];
    const float* by2x = (const float*)d_in[6];
    const float* Wx2y = (const float*)d_in[7];
    const float* bx2y = (const float*)d_in[8];
    float* Y = (float*)d_out;

    cudaFuncSetAttribute(fused_passA, cudaFuncAttributeMaxDynamicSharedMemorySize, KA_SMEM);
    cudaFuncSetAttribute(fused_passB, cudaFuncAttributeMaxDynamicSharedMemorySize, KB_SMEM);

    params_kernel<<<1, 128>>>(lrc, lic);
    prep_kernel<<<64, 256>>>(B, Wx2y);
    x0_kernel<<<NB, 128>>>(y0, Wy2x, by2x);

    fused_passA<<<NCHUNK * 8, 256, KA_SMEM>>>(U);
    carry_kernel<<<NB * NPAIR / 256, 256>>>();
    fused_passB<<<NCHUNK * 8, 256, KB_SMEM>>>(bx2y, Y);
}